// round 1
// baseline (speedup 1.0000x reference)
#include <cuda_runtime.h>
#include <math.h>

#define B_  4
#define T_  2048
#define D_  1024
#define H_  16
#define DH_ 64
#define M_  (B_ * T_)   // 8192

// ---------------- scratch (device globals; no allocation allowed) ----------
__device__ float g_q[(size_t)B_ * H_ * T_ * DH_];   // (B,H,T,dh) 33.5 MB
__device__ float g_k[(size_t)B_ * T_ * DH_];        // (B,T,dh)    2 MB
__device__ float g_v[(size_t)B_ * T_ * DH_];        // (B,T,dh)    2 MB
__device__ float g_ctx[(size_t)B_ * T_ * D_];       // (B,T,D)  33.5 MB

// ============================================================================
// Big GEMM: C(M,N) = A(M,K) @ W(N,K)^T + bias.  BM=BN=128, BK=16, 256 thr, 8x8.
// MODE 0: A = g_ctx, write C param (row-major M x N)      [output projection]
// MODE 1: A = param, write g_q in (B,H,T,dh) layout        [Q projection]
// ============================================================================
template <int MODE>
__global__ __launch_bounds__(256, 2)
void gemm128_kernel(const float* __restrict__ Ain,
                    const float* __restrict__ W,
                    const float* __restrict__ bias,
                    float* __restrict__ C)
{
    const int K = D_;
    const int N = D_;
    __shared__ float As[16][128 + 4];
    __shared__ float Ws[16][128 + 4];

    const int bm  = blockIdx.y * 128;
    const int bn  = blockIdx.x * 128;
    const int tid = threadIdx.x;
    const int rt  = tid >> 4;   // 0..15 -> 8 rows each
    const int ct  = tid & 15;   // 0..15 -> 8 cols each

    const float* A = (MODE == 0) ? g_ctx : Ain;

    float acc[8][8];
#pragma unroll
    for (int i = 0; i < 8; ++i)
#pragma unroll
        for (int j = 0; j < 8; ++j) acc[i][j] = 0.0f;

    for (int k0 = 0; k0 < K; k0 += 16) {
        // load A tile 128x16 (2 float4 per thread), transposed into As[k][m]
#pragma unroll
        for (int l = 0; l < 2; ++l) {
            int p  = tid + l * 256;
            int r  = p >> 2;
            int c4 = (p & 3) * 4;
            float4 v = *reinterpret_cast<const float4*>(
                &A[(size_t)(bm + r) * K + k0 + c4]);
            As[c4 + 0][r] = v.x; As[c4 + 1][r] = v.y;
            As[c4 + 2][r] = v.z; As[c4 + 3][r] = v.w;
        }
        // load W tile 128x16 (rows = output cols n), transposed into Ws[k][n]
#pragma unroll
        for (int l = 0; l < 2; ++l) {
            int p  = tid + l * 256;
            int r  = p >> 2;
            int c4 = (p & 3) * 4;
            float4 v = *reinterpret_cast<const float4*>(
                &W[(size_t)(bn + r) * K + k0 + c4]);
            Ws[c4 + 0][r] = v.x; Ws[c4 + 1][r] = v.y;
            Ws[c4 + 2][r] = v.z; Ws[c4 + 3][r] = v.w;
        }
        __syncthreads();

#pragma unroll
        for (int kk = 0; kk < 16; ++kk) {
            float4 a0 = *reinterpret_cast<const float4*>(&As[kk][rt * 8]);
            float4 a1 = *reinterpret_cast<const float4*>(&As[kk][rt * 8 + 4]);
            float4 b0 = *reinterpret_cast<const float4*>(&Ws[kk][ct * 8]);
            float4 b1 = *reinterpret_cast<const float4*>(&Ws[kk][ct * 8 + 4]);
            float a[8] = {a0.x, a0.y, a0.z, a0.w, a1.x, a1.y, a1.z, a1.w};
            float b[8] = {b0.x, b0.y, b0.z, b0.w, b1.x, b1.y, b1.z, b1.w};
#pragma unroll
            for (int i = 0; i < 8; ++i)
#pragma unroll
                for (int j = 0; j < 8; ++j) acc[i][j] += a[i] * b[j];
        }
        __syncthreads();
    }

    // epilogue
#pragma unroll
    for (int i = 0; i < 8; ++i) {
        int m = bm + rt * 8 + i;
        if (MODE == 0) {
#pragma unroll
            for (int j = 0; j < 8; j += 4) {
                int n = bn + ct * 8 + j;
                float4 v = make_float4(acc[i][j + 0] + bias[n + 0],
                                       acc[i][j + 1] + bias[n + 1],
                                       acc[i][j + 2] + bias[n + 2],
                                       acc[i][j + 3] + bias[n + 3]);
                *reinterpret_cast<float4*>(&C[(size_t)m * N + n]) = v;
            }
        } else {
            int b = m / T_;
            int t = m % T_;
            int n0 = bn + ct * 8;
            int h  = n0 >> 6;
            int d0 = n0 & 63;
#pragma unroll
            for (int j = 0; j < 8; j += 4) {
                int n = n0 + j;
                float4 v = make_float4(acc[i][j + 0] + bias[n + 0],
                                       acc[i][j + 1] + bias[n + 1],
                                       acc[i][j + 2] + bias[n + 2],
                                       acc[i][j + 3] + bias[n + 3]);
                size_t base = (((size_t)b * H_ + h) * T_ + t) * DH_ + d0 + j;
                *reinterpret_cast<float4*>(&g_q[base]) = v;
            }
        }
    }
}

// ============================================================================
// K/V projection: out(M,64) = A(M,1024) @ W(64,1024)^T + bias.
// BM=128, BN=64, BK=16, 256 thr, 8x4 per thread. blockIdx.x: 0 = K, 1 = V.
// ============================================================================
__global__ __launch_bounds__(256, 2)
void kvproj_kernel(const float* __restrict__ xk, const float* __restrict__ Wk,
                   const float* __restrict__ bk,
                   const float* __restrict__ xv, const float* __restrict__ Wv,
                   const float* __restrict__ bv)
{
    const int K = D_;
    __shared__ float As[16][128 + 4];
    __shared__ float Ws[16][64 + 4];

    const bool isV = (blockIdx.x == 1);
    const float* A    = isV ? xv : xk;
    const float* W    = isV ? Wv : Wk;
    const float* bias = isV ? bv : bk;
    float* out        = isV ? g_v : g_k;

    const int bm  = blockIdx.y * 128;
    const int tid = threadIdx.x;
    const int rt  = tid >> 4;
    const int ct  = tid & 15;

    float acc[8][4];
#pragma unroll
    for (int i = 0; i < 8; ++i)
#pragma unroll
        for (int j = 0; j < 4; ++j) acc[i][j] = 0.0f;

    for (int k0 = 0; k0 < K; k0 += 16) {
#pragma unroll
        for (int l = 0; l < 2; ++l) {
            int p  = tid + l * 256;
            int r  = p >> 2;
            int c4 = (p & 3) * 4;
            float4 v = *reinterpret_cast<const float4*>(
                &A[(size_t)(bm + r) * K + k0 + c4]);
            As[c4 + 0][r] = v.x; As[c4 + 1][r] = v.y;
            As[c4 + 2][r] = v.z; As[c4 + 3][r] = v.w;
        }
        {   // W tile 64x16 -> 256 float4 -> one per thread
            int r  = tid >> 2;
            int c4 = (tid & 3) * 4;
            float4 v = *reinterpret_cast<const float4*>(
                &W[(size_t)r * K + k0 + c4]);
            Ws[c4 + 0][r] = v.x; Ws[c4 + 1][r] = v.y;
            Ws[c4 + 2][r] = v.z; Ws[c4 + 3][r] = v.w;
        }
        __syncthreads();

#pragma unroll
        for (int kk = 0; kk < 16; ++kk) {
            float4 a0 = *reinterpret_cast<const float4*>(&As[kk][rt * 8]);
            float4 a1 = *reinterpret_cast<const float4*>(&As[kk][rt * 8 + 4]);
            float4 b0 = *reinterpret_cast<const float4*>(&Ws[kk][ct * 4]);
            float a[8] = {a0.x, a0.y, a0.z, a0.w, a1.x, a1.y, a1.z, a1.w};
            float b[4] = {b0.x, b0.y, b0.z, b0.w};
#pragma unroll
            for (int i = 0; i < 8; ++i)
#pragma unroll
                for (int j = 0; j < 4; ++j) acc[i][j] += a[i] * b[j];
        }
        __syncthreads();
    }

#pragma unroll
    for (int i = 0; i < 8; ++i) {
        int m = bm + rt * 8 + i;
        int n = ct * 4;
        float4 v = make_float4(acc[i][0] + bias[n + 0],
                               acc[i][1] + bias[n + 1],
                               acc[i][2] + bias[n + 2],
                               acc[i][3] + bias[n + 3]);
        *reinterpret_cast<float4*>(&out[(size_t)m * DH_ + n]) = v;
    }
}

// ============================================================================
// RoPE on g_q (B,H,T,dh) and g_k (B,T,dh). One thread per rotation pair.
// Precise powf/sinf/cosf to match the fp32 reference within error budget.
// ============================================================================
__global__ void rope_kernel()
{
    const int QP = B_ * H_ * T_ * 32;
    const int KP = B_ * T_ * 32;
    int idx = blockIdx.x * blockDim.x + threadIdx.x;
    if (idx >= QP + KP) return;

    float* buf;
    int i, t;
    size_t base;
    if (idx < QP) {
        i = idx & 31;
        t = (idx >> 5) % T_;
        int bh = idx / (32 * T_);
        base = ((size_t)bh * T_ + t) * DH_;
        buf = g_q;
    } else {
        int p = idx - QP;
        i = p & 31;
        int bt = p >> 5;
        t = bt % T_;
        base = (size_t)bt * DH_;
        buf = g_k;
    }
    float inv = powf(10000.0f, -(float)i / 32.0f);
    float ang = (float)t * inv;
    float s = sinf(ang);
    float c = cosf(ang);
    float x1 = buf[base + i];
    float x2 = buf[base + i + 32];
    buf[base + i]      = x1 * c - x2 * s;
    buf[base + i + 32] = x2 * c + x1 * s;
}

// ============================================================================
// Flash attention, fp32, non-causal. 64 queries x 64 keys tiles, dh=64.
// 256 threads as 16x16, 4x4 micro-tile. Online softmax via 16-lane shuffles.
// Writes ctx in (B,T,D) layout for the output projection.
// ============================================================================
#define APITCH 68   // 64 + 4 pad, keeps float4 alignment, breaks bank collisions
#define ATTN_SMEM (4 * 64 * APITCH * 4)

__global__ __launch_bounds__(256, 2)
void attn_kernel()
{
    extern __shared__ float smem[];
    float* Qs = smem;                  // [d][r]
    float* Ks = Qs + 64 * APITCH;      // [d][s]
    float* Vs = Ks + 64 * APITCH;      // [s][c]
    float* Ps = Vs + 64 * APITCH;      // [r][s]

    const int qt = blockIdx.x;
    const int h  = blockIdx.y;
    const int b  = blockIdx.z;
    const int tid = threadIdx.x;
    const int ty = tid >> 4;   // row group (4 rows)
    const int tx = tid & 15;   // col group (4 cols)

    // load Q tile (scaled by 1/sqrt(dh)), transposed to Qs[d][r]
    const size_t qbase = (((size_t)b * H_ + h) * T_ + (size_t)qt * 64) * DH_;
#pragma unroll
    for (int l = 0; l < 4; ++l) {
        int p  = tid + l * 256;
        int r  = p >> 4;
        int d0 = (p & 15) * 4;
        float4 v = *reinterpret_cast<const float4*>(&g_q[qbase + (size_t)r * DH_ + d0]);
        Qs[(d0 + 0) * APITCH + r] = v.x * 0.125f;
        Qs[(d0 + 1) * APITCH + r] = v.y * 0.125f;
        Qs[(d0 + 2) * APITCH + r] = v.z * 0.125f;
        Qs[(d0 + 3) * APITCH + r] = v.w * 0.125f;
    }

    float o[4][4];
    float m_i[4], l_i[4];
#pragma unroll
    for (int i = 0; i < 4; ++i) {
        m_i[i] = -1e30f;
        l_i[i] = 0.0f;
#pragma unroll
        for (int j = 0; j < 4; ++j) o[i][j] = 0.0f;
    }

    const size_t kvbase = ((size_t)b * T_) * DH_;

    for (int kt = 0; kt < T_ / 64; ++kt) {
        __syncthreads();   // previous iteration done with Ks/Vs/Ps
        // load K tile transposed -> Ks[d][s]; V tile direct -> Vs[s][c]
#pragma unroll
        for (int l = 0; l < 4; ++l) {
            int p  = tid + l * 256;
            int s  = p >> 4;
            int d0 = (p & 15) * 4;
            size_t g = kvbase + ((size_t)kt * 64 + s) * DH_ + d0;
            float4 kv = *reinterpret_cast<const float4*>(&g_k[g]);
            Ks[(d0 + 0) * APITCH + s] = kv.x;
            Ks[(d0 + 1) * APITCH + s] = kv.y;
            Ks[(d0 + 2) * APITCH + s] = kv.z;
            Ks[(d0 + 3) * APITCH + s] = kv.w;
            float4 vv = *reinterpret_cast<const float4*>(&g_v[g]);
            *reinterpret_cast<float4*>(&Vs[s * APITCH + d0]) = vv;
        }
        __syncthreads();

        // S = Q @ K^T  (4x4 per thread)
        float sacc[4][4];
#pragma unroll
        for (int i = 0; i < 4; ++i)
#pragma unroll
            for (int j = 0; j < 4; ++j) sacc[i][j] = 0.0f;

#pragma unroll 8
        for (int d = 0; d < 64; ++d) {
            float4 a = *reinterpret_cast<const float4*>(&Qs[d * APITCH + ty * 4]);
            float4 bb = *reinterpret_cast<const float4*>(&Ks[d * APITCH + tx * 4]);
            float av[4] = {a.x, a.y, a.z, a.w};
            float bv_[4] = {bb.x, bb.y, bb.z, bb.w};
#pragma unroll
            for (int i = 0; i < 4; ++i)
#pragma unroll
                for (int j = 0; j < 4; ++j) sacc[i][j] += av[i] * bv_[j];
        }

        // online softmax per row (rows distributed over ty; full row across tx)
#pragma unroll
        for (int i = 0; i < 4; ++i) {
            float mx = fmaxf(fmaxf(sacc[i][0], sacc[i][1]),
                             fmaxf(sacc[i][2], sacc[i][3]));
#pragma unroll
            for (int off = 8; off > 0; off >>= 1)
                mx = fmaxf(mx, __shfl_xor_sync(0xffffffffu, mx, off));
            float mnew = fmaxf(m_i[i], mx);
            float alpha = __expf(m_i[i] - mnew);
            m_i[i] = mnew;
            float rs = 0.0f;
#pragma unroll
            for (int j = 0; j < 4; ++j) {
                float p = __expf(sacc[i][j] - mnew);
                sacc[i][j] = p;
                rs += p;
            }
#pragma unroll
            for (int off = 8; off > 0; off >>= 1)
                rs += __shfl_xor_sync(0xffffffffu, rs, off);
            l_i[i] = l_i[i] * alpha + rs;
#pragma unroll
            for (int j = 0; j < 4; ++j) o[i][j] *= alpha;
        }

        // stage P -> Ps[r][s] (float4 stores, conflict-free)
#pragma unroll
        for (int i = 0; i < 4; ++i) {
            float4 v = make_float4(sacc[i][0], sacc[i][1], sacc[i][2], sacc[i][3]);
            *reinterpret_cast<float4*>(&Ps[(ty * 4 + i) * APITCH + tx * 4]) = v;
        }
        __syncthreads();

        // O += P @ V
#pragma unroll 4
        for (int s0 = 0; s0 < 64; s0 += 4) {
            float pc[4][4];
#pragma unroll
            for (int i = 0; i < 4; ++i)
                *reinterpret_cast<float4*>(&pc[i][0]) =
                    *reinterpret_cast<const float4*>(&Ps[(ty * 4 + i) * APITCH + s0]);
#pragma unroll
            for (int u = 0; u < 4; ++u) {
                float4 vb = *reinterpret_cast<const float4*>(&Vs[(s0 + u) * APITCH + tx * 4]);
                float vv[4] = {vb.x, vb.y, vb.z, vb.w};
#pragma unroll
                for (int i = 0; i < 4; ++i)
#pragma unroll
                    for (int j = 0; j < 4; ++j) o[i][j] += pc[i][u] * vv[j];
            }
        }
    }

    // normalize + write ctx (B,T,D)
#pragma unroll
    for (int i = 0; i < 4; ++i) {
        float inv = 1.0f / l_i[i];
        int r = ty * 4 + i;
        size_t base = ((size_t)b * T_ + (size_t)qt * 64 + r) * D_ + h * 64 + tx * 4;
        float4 v = make_float4(o[i][0] * inv, o[i][1] * inv,
                               o[i][2] * inv, o[i][3] * inv);
        *reinterpret_cast<float4*>(&g_ctx[base]) = v;
    }
}

// ============================================================================
extern "C" void kernel_launch(void* const* d_in, const int* in_sizes, int n_in,
                              void* d_out, int out_size)
{
    (void)in_sizes; (void)n_in; (void)out_size;
    const float* x  = (const float*)d_in[0];
    const float* xk = (const float*)d_in[1];
    const float* xv = (const float*)d_in[2];
    const float* Wq = (const float*)d_in[3];
    const float* bq = (const float*)d_in[4];
    const float* Wk = (const float*)d_in[5];
    const float* bk = (const float*)d_in[6];
    const float* Wv = (const float*)d_in[7];
    const float* bv = (const float*)d_in[8];
    const float* Wo = (const float*)d_in[9];
    const float* bo = (const float*)d_in[10];
    float* out = (float*)d_out;

    cudaFuncSetAttribute(attn_kernel,
                         cudaFuncAttributeMaxDynamicSharedMemorySize, ATTN_SMEM);

    // Q projection -> g_q (B,H,T,dh)
    gemm128_kernel<1><<<dim3(D_ / 128, M_ / 128), 256>>>(x, Wq, bq, nullptr);
    // K and V projections -> g_k, g_v
    kvproj_kernel<<<dim3(2, M_ / 128), 256>>>(xk, Wk, bk, xv, Wv, bv);
    // RoPE in-place on g_q and g_k
    {
        int total = B_ * H_ * T_ * 32 + B_ * T_ * 32;
        rope_kernel<<<(total + 255) / 256, 256>>>();
    }
    // attention -> g_ctx (B,T,D)
    attn_kernel<<<dim3(T_ / 64, H_, B_), 256, ATTN_SMEM>>>();
    // output projection -> d_out
    gemm128_kernel<0><<<dim3(D_ / 128, M_ / 128), 256>>>(nullptr, Wo, bo, out);
}

// round 3
// speedup vs baseline: 1.8530x; 1.8530x over previous
#include <cuda_runtime.h>
#include <math.h>
#include <stdint.h>

#define B_  4
#define T_  2048
#define D_  1024
#define H_  16
#define DH_ 64
#define M_  (B_ * T_)   // 8192

// ---------------- scratch (device globals; no allocation allowed) ----------
__device__ float g_q[(size_t)B_ * H_ * T_ * DH_];   // (B,H,T,dh)
__device__ float g_k[(size_t)B_ * T_ * DH_];        // (B,T,dh)
__device__ float g_v[(size_t)B_ * T_ * DH_];        // (B,T,dh)
__device__ float g_ctx[(size_t)B_ * T_ * D_];       // (B,T,D)

// ============================================================================
// Big GEMM: C(M,N) = A(M,K) @ W(N,K)^T + bias.  BM=BN=128, BK=16, 256 thr, 8x8.
// MODE 0: A = g_ctx, write C param (row-major M x N)      [output projection]
// MODE 1: A = param, write g_q in (B,H,T,dh) layout        [Q projection]
// ============================================================================
template <int MODE>
__global__ __launch_bounds__(256, 2)
void gemm128_kernel(const float* __restrict__ Ain,
                    const float* __restrict__ W,
                    const float* __restrict__ bias,
                    float* __restrict__ C)
{
    const int K = D_;
    const int N = D_;
    __shared__ float As[16][128 + 4];
    __shared__ float Ws[16][128 + 4];

    const int bm  = blockIdx.y * 128;
    const int bn  = blockIdx.x * 128;
    const int tid = threadIdx.x;
    const int rt  = tid >> 4;
    const int ct  = tid & 15;

    const float* A = (MODE == 0) ? g_ctx : Ain;

    float acc[8][8];
#pragma unroll
    for (int i = 0; i < 8; ++i)
#pragma unroll
        for (int j = 0; j < 8; ++j) acc[i][j] = 0.0f;

    for (int k0 = 0; k0 < K; k0 += 16) {
#pragma unroll
        for (int l = 0; l < 2; ++l) {
            int p  = tid + l * 256;
            int r  = p >> 2;
            int c4 = (p & 3) * 4;
            float4 v = *reinterpret_cast<const float4*>(
                &A[(size_t)(bm + r) * K + k0 + c4]);
            As[c4 + 0][r] = v.x; As[c4 + 1][r] = v.y;
            As[c4 + 2][r] = v.z; As[c4 + 3][r] = v.w;
        }
#pragma unroll
        for (int l = 0; l < 2; ++l) {
            int p  = tid + l * 256;
            int r  = p >> 2;
            int c4 = (p & 3) * 4;
            float4 v = *reinterpret_cast<const float4*>(
                &W[(size_t)(bn + r) * K + k0 + c4]);
            Ws[c4 + 0][r] = v.x; Ws[c4 + 1][r] = v.y;
            Ws[c4 + 2][r] = v.z; Ws[c4 + 3][r] = v.w;
        }
        __syncthreads();

#pragma unroll
        for (int kk = 0; kk < 16; ++kk) {
            float4 a0 = *reinterpret_cast<const float4*>(&As[kk][rt * 8]);
            float4 a1 = *reinterpret_cast<const float4*>(&As[kk][rt * 8 + 4]);
            float4 b0 = *reinterpret_cast<const float4*>(&Ws[kk][ct * 8]);
            float4 b1 = *reinterpret_cast<const float4*>(&Ws[kk][ct * 8 + 4]);
            float a[8] = {a0.x, a0.y, a0.z, a0.w, a1.x, a1.y, a1.z, a1.w};
            float b[8] = {b0.x, b0.y, b0.z, b0.w, b1.x, b1.y, b1.z, b1.w};
#pragma unroll
            for (int i = 0; i < 8; ++i)
#pragma unroll
                for (int j = 0; j < 8; ++j) acc[i][j] += a[i] * b[j];
        }
        __syncthreads();
    }

#pragma unroll
    for (int i = 0; i < 8; ++i) {
        int m = bm + rt * 8 + i;
        if (MODE == 0) {
#pragma unroll
            for (int j = 0; j < 8; j += 4) {
                int n = bn + ct * 8 + j;
                float4 v = make_float4(acc[i][j + 0] + bias[n + 0],
                                       acc[i][j + 1] + bias[n + 1],
                                       acc[i][j + 2] + bias[n + 2],
                                       acc[i][j + 3] + bias[n + 3]);
                *reinterpret_cast<float4*>(&C[(size_t)m * N + n]) = v;
            }
        } else {
            int b = m / T_;
            int t = m % T_;
            int n0 = bn + ct * 8;
            int h  = n0 >> 6;
            int d0 = n0 & 63;
#pragma unroll
            for (int j = 0; j < 8; j += 4) {
                int n = n0 + j;
                float4 v = make_float4(acc[i][j + 0] + bias[n + 0],
                                       acc[i][j + 1] + bias[n + 1],
                                       acc[i][j + 2] + bias[n + 2],
                                       acc[i][j + 3] + bias[n + 3]);
                size_t base = (((size_t)b * H_ + h) * T_ + t) * DH_ + d0 + j;
                *reinterpret_cast<float4*>(&g_q[base]) = v;
            }
        }
    }
}

// ============================================================================
// K/V projection: out(M,64) = A(M,1024) @ W(64,1024)^T + bias.
// ============================================================================
__global__ __launch_bounds__(256, 2)
void kvproj_kernel(const float* __restrict__ xk, const float* __restrict__ Wk,
                   const float* __restrict__ bk,
                   const float* __restrict__ xv, const float* __restrict__ Wv,
                   const float* __restrict__ bv)
{
    const int K = D_;
    __shared__ float As[16][128 + 4];
    __shared__ float Ws[16][64 + 4];

    const bool isV = (blockIdx.x == 1);
    const float* A    = isV ? xv : xk;
    const float* W    = isV ? Wv : Wk;
    const float* bias = isV ? bv : bk;
    float* out        = isV ? g_v : g_k;

    const int bm  = blockIdx.y * 128;
    const int tid = threadIdx.x;
    const int rt  = tid >> 4;
    const int ct  = tid & 15;

    float acc[8][4];
#pragma unroll
    for (int i = 0; i < 8; ++i)
#pragma unroll
        for (int j = 0; j < 4; ++j) acc[i][j] = 0.0f;

    for (int k0 = 0; k0 < K; k0 += 16) {
#pragma unroll
        for (int l = 0; l < 2; ++l) {
            int p  = tid + l * 256;
            int r  = p >> 2;
            int c4 = (p & 3) * 4;
            float4 v = *reinterpret_cast<const float4*>(
                &A[(size_t)(bm + r) * K + k0 + c4]);
            As[c4 + 0][r] = v.x; As[c4 + 1][r] = v.y;
            As[c4 + 2][r] = v.z; As[c4 + 3][r] = v.w;
        }
        {
            int r  = tid >> 2;
            int c4 = (tid & 3) * 4;
            float4 v = *reinterpret_cast<const float4*>(
                &W[(size_t)r * K + k0 + c4]);
            Ws[c4 + 0][r] = v.x; Ws[c4 + 1][r] = v.y;
            Ws[c4 + 2][r] = v.z; Ws[c4 + 3][r] = v.w;
        }
        __syncthreads();

#pragma unroll
        for (int kk = 0; kk < 16; ++kk) {
            float4 a0 = *reinterpret_cast<const float4*>(&As[kk][rt * 8]);
            float4 a1 = *reinterpret_cast<const float4*>(&As[kk][rt * 8 + 4]);
            float4 b0 = *reinterpret_cast<const float4*>(&Ws[kk][ct * 4]);
            float a[8] = {a0.x, a0.y, a0.z, a0.w, a1.x, a1.y, a1.z, a1.w};
            float b[4] = {b0.x, b0.y, b0.z, b0.w};
#pragma unroll
            for (int i = 0; i < 8; ++i)
#pragma unroll
                for (int j = 0; j < 4; ++j) acc[i][j] += a[i] * b[j];
        }
        __syncthreads();
    }

#pragma unroll
    for (int i = 0; i < 8; ++i) {
        int m = bm + rt * 8 + i;
        int n = ct * 4;
        float4 v = make_float4(acc[i][0] + bias[n + 0],
                               acc[i][1] + bias[n + 1],
                               acc[i][2] + bias[n + 2],
                               acc[i][3] + bias[n + 3]);
        *reinterpret_cast<float4*>(&out[(size_t)m * DH_ + n]) = v;
    }
}

// ============================================================================
// RoPE on g_q (B,H,T,dh) and g_k (B,T,dh). One thread per rotation pair.
// ============================================================================
__global__ void rope_kernel()
{
    const int QP = B_ * H_ * T_ * 32;
    const int KP = B_ * T_ * 32;
    int idx = blockIdx.x * blockDim.x + threadIdx.x;
    if (idx >= QP + KP) return;

    float* buf;
    int i, t;
    size_t base;
    if (idx < QP) {
        i = idx & 31;
        t = (idx >> 5) % T_;
        int bh = idx / (32 * T_);
        base = ((size_t)bh * T_ + t) * DH_;
        buf = g_q;
    } else {
        int p = idx - QP;
        i = p & 31;
        int bt = p >> 5;
        t = bt % T_;
        base = (size_t)bt * DH_;
        buf = g_k;
    }
    float inv = powf(10000.0f, -(float)i / 32.0f);
    float ang = (float)t * inv;
    float s = sinf(ang);
    float c = cosf(ang);
    float x1 = buf[base + i];
    float x2 = buf[base + i + 32];
    buf[base + i]      = x1 * c - x2 * s;
    buf[base + i + 32] = x2 * c + x1 * s;
}

// ============================================================================
// Tensor-core flash attention (tf32 mma.sync m16n8k8, fp32 accumulate).
// 128 threads = 4 warps. Br=64 (16 rows/warp), Bc=64, dh=64.
// Q fragments resident in registers; K/V staged in smem as tf32 bits;
// P routed through per-warp-private smem rows for C->A layout conversion.
// ============================================================================
#define KP_ 68   // K smem pitch (words): B-load addr (nc*8+g)*68+kc*8+tig -> conflict-free
#define VP_ 72   // V smem pitch: B-load addr (kc*8+tig)*72+nc*8+g -> conflict-free
#define PP_ 68   // P smem pitch: A-load addr (row)*68+kc*8+tig -> conflict-free
#define ATTN_SMEM ((64 * (KP_ + VP_ + PP_)) * 4)

__device__ __forceinline__ uint32_t f2tf32(float x)
{
    uint32_t r;
    asm("cvt.rna.tf32.f32 %0, %1;" : "=r"(r) : "f"(x));
    return r;
}

__device__ __forceinline__ void mma_tf32(float c[4],
                                         const uint32_t a[4],
                                         uint32_t b0, uint32_t b1)
{
    asm volatile(
        "mma.sync.aligned.m16n8k8.row.col.f32.tf32.tf32.f32 "
        "{%0,%1,%2,%3}, {%4,%5,%6,%7}, {%8,%9}, {%0,%1,%2,%3};"
        : "+f"(c[0]), "+f"(c[1]), "+f"(c[2]), "+f"(c[3])
        : "r"(a[0]), "r"(a[1]), "r"(a[2]), "r"(a[3]), "r"(b0), "r"(b1));
}

__global__ __launch_bounds__(128)
void attn_tc_kernel()
{
    extern __shared__ uint32_t smu[];
    uint32_t* Ks = smu;                 // [key][d], pitch KP_
    uint32_t* Vs = Ks + 64 * KP_;       // [key][d], pitch VP_
    uint32_t* Ps = Vs + 64 * VP_;       // [row][key], pitch PP_

    const int qt  = blockIdx.x;
    const int h   = blockIdx.y;
    const int b   = blockIdx.z;
    const int tid = threadIdx.x;
    const int w    = tid >> 5;
    const int lane = tid & 31;
    const int g    = lane >> 2;   // group id 0..7
    const int tig  = lane & 3;    // thread in group 0..3

    const int row0 = w * 16 + g;  // local row for a0/c0; row0+8 for a1/c2

    // ---- Q fragments (scaled by 1/sqrt(dh), tf32-rounded), resident -------
    const size_t qbase = (((size_t)b * H_ + h) * T_ + (size_t)qt * 64) * DH_;
    uint32_t qa[8][4];
#pragma unroll
    for (int kc = 0; kc < 8; ++kc) {
        int d0 = kc * 8 + tig;
        qa[kc][0] = f2tf32(g_q[qbase + (size_t)row0 * DH_ + d0] * 0.125f);
        qa[kc][1] = f2tf32(g_q[qbase + (size_t)(row0 + 8) * DH_ + d0] * 0.125f);
        qa[kc][2] = f2tf32(g_q[qbase + (size_t)row0 * DH_ + d0 + 4] * 0.125f);
        qa[kc][3] = f2tf32(g_q[qbase + (size_t)(row0 + 8) * DH_ + d0 + 4] * 0.125f);
    }

    float o[8][4];
#pragma unroll
    for (int nc = 0; nc < 8; ++nc)
#pragma unroll
        for (int j = 0; j < 4; ++j) o[nc][j] = 0.0f;
    float m0 = -1e30f, m1 = -1e30f, l0 = 0.0f, l1 = 0.0f;

    const size_t kvbase = (size_t)b * T_ * DH_;

    for (int kt = 0; kt < T_ / 64; ++kt) {
        __syncthreads();   // previous iteration done with Ks/Vs
        // ---- load K,V tiles (64x64 f32 each) as tf32 bits ------------------
#pragma unroll
        for (int l = 0; l < 8; ++l) {
            int p  = tid + l * 128;     // 0..1023
            int r  = p >> 4;            // key 0..63
            int d0 = (p & 15) * 4;
            size_t ga = kvbase + ((size_t)kt * 64 + r) * DH_ + d0;
            float4 kv = *reinterpret_cast<const float4*>(&g_k[ga]);
            uint4 ku = make_uint4(f2tf32(kv.x), f2tf32(kv.y),
                                  f2tf32(kv.z), f2tf32(kv.w));
            *reinterpret_cast<uint4*>(&Ks[r * KP_ + d0]) = ku;
            float4 vv = *reinterpret_cast<const float4*>(&g_v[ga]);
            uint4 vu = make_uint4(f2tf32(vv.x), f2tf32(vv.y),
                                  f2tf32(vv.z), f2tf32(vv.w));
            *reinterpret_cast<uint4*>(&Vs[r * VP_ + d0]) = vu;
        }
        __syncthreads();

        // ---- S = Q @ K^T ---------------------------------------------------
        float s[8][4];
#pragma unroll
        for (int nc = 0; nc < 8; ++nc) {
            s[nc][0] = s[nc][1] = s[nc][2] = s[nc][3] = 0.0f;
#pragma unroll
            for (int kc = 0; kc < 8; ++kc) {
                const uint32_t* krow = &Ks[(nc * 8 + g) * KP_ + kc * 8];
                mma_tf32(s[nc], qa[kc], krow[tig], krow[tig + 4]);
            }
        }

        // ---- online softmax (rows row0 and row0+8) -------------------------
        float mx0 = -1e30f, mx1 = -1e30f;
#pragma unroll
        for (int nc = 0; nc < 8; ++nc) {
            mx0 = fmaxf(mx0, fmaxf(s[nc][0], s[nc][1]));
            mx1 = fmaxf(mx1, fmaxf(s[nc][2], s[nc][3]));
        }
#pragma unroll
        for (int off = 1; off < 4; off <<= 1) {
            mx0 = fmaxf(mx0, __shfl_xor_sync(0xffffffffu, mx0, off));
            mx1 = fmaxf(mx1, __shfl_xor_sync(0xffffffffu, mx1, off));
        }
        float mn0 = fmaxf(m0, mx0), mn1 = fmaxf(m1, mx1);
        float al0 = __expf(m0 - mn0), al1 = __expf(m1 - mn1);
        m0 = mn0; m1 = mn1;

        float rs0 = 0.0f, rs1 = 0.0f;
#pragma unroll
        for (int nc = 0; nc < 8; ++nc) {
            float p0 = __expf(s[nc][0] - mn0);
            float p1 = __expf(s[nc][1] - mn0);
            float p2 = __expf(s[nc][2] - mn1);
            float p3 = __expf(s[nc][3] - mn1);
            rs0 += p0 + p1;
            rs1 += p2 + p3;
            int col = nc * 8 + 2 * tig;
            *reinterpret_cast<uint2*>(&Ps[row0 * PP_ + col]) =
                make_uint2(f2tf32(p0), f2tf32(p1));
            *reinterpret_cast<uint2*>(&Ps[(row0 + 8) * PP_ + col]) =
                make_uint2(f2tf32(p2), f2tf32(p3));
        }
#pragma unroll
        for (int off = 1; off < 4; off <<= 1) {
            rs0 += __shfl_xor_sync(0xffffffffu, rs0, off);
            rs1 += __shfl_xor_sync(0xffffffffu, rs1, off);
        }
        l0 = l0 * al0 + rs0;
        l1 = l1 * al1 + rs1;
#pragma unroll
        for (int nc = 0; nc < 8; ++nc) {
            o[nc][0] *= al0; o[nc][1] *= al0;
            o[nc][2] *= al1; o[nc][3] *= al1;
        }
        __syncwarp();   // Ps rows are per-warp private

        // ---- O += P @ V ----------------------------------------------------
        uint32_t pa[8][4];
#pragma unroll
        for (int kc = 0; kc < 8; ++kc) {
            int d0 = kc * 8 + tig;
            pa[kc][0] = Ps[row0 * PP_ + d0];
            pa[kc][1] = Ps[(row0 + 8) * PP_ + d0];
            pa[kc][2] = Ps[row0 * PP_ + d0 + 4];
            pa[kc][3] = Ps[(row0 + 8) * PP_ + d0 + 4];
        }
#pragma unroll
        for (int nc = 0; nc < 8; ++nc) {
#pragma unroll
            for (int kc = 0; kc < 8; ++kc) {
                uint32_t b0 = Vs[(kc * 8 + tig) * VP_ + nc * 8 + g];
                uint32_t b1 = Vs[(kc * 8 + tig + 4) * VP_ + nc * 8 + g];
                mma_tf32(o[nc], pa[kc], b0, b1);
            }
        }
        __syncwarp();   // done reading Ps before next iteration overwrites
    }

    // ---- normalize + write ctx (B,T,D) -------------------------------------
    float inv0 = 1.0f / l0, inv1 = 1.0f / l1;
    size_t cbase0 = ((size_t)b * T_ + (size_t)qt * 64 + row0) * D_ + h * 64;
    size_t cbase1 = ((size_t)b * T_ + (size_t)qt * 64 + row0 + 8) * D_ + h * 64;
#pragma unroll
    for (int nc = 0; nc < 8; ++nc) {
        int col = nc * 8 + 2 * tig;
        *reinterpret_cast<float2*>(&g_ctx[cbase0 + col]) =
            make_float2(o[nc][0] * inv0, o[nc][1] * inv0);
        *reinterpret_cast<float2*>(&g_ctx[cbase1 + col]) =
            make_float2(o[nc][2] * inv1, o[nc][3] * inv1);
    }
}

// ============================================================================
extern "C" void kernel_launch(void* const* d_in, const int* in_sizes, int n_in,
                              void* d_out, int out_size)
{
    (void)in_sizes; (void)n_in; (void)out_size;
    const float* x  = (const float*)d_in[0];
    const float* xk = (const float*)d_in[1];
    const float* xv = (const float*)d_in[2];
    const float* Wq = (const float*)d_in[3];
    const float* bq = (const float*)d_in[4];
    const float* Wk = (const float*)d_in[5];
    const float* bk = (const float*)d_in[6];
    const float* Wv = (const float*)d_in[7];
    const float* bv = (const float*)d_in[8];
    const float* Wo = (const float*)d_in[9];
    const float* bo = (const float*)d_in[10];
    float* out = (float*)d_out;

    cudaFuncSetAttribute(attn_tc_kernel,
                         cudaFuncAttributeMaxDynamicSharedMemorySize, ATTN_SMEM);

    // Q projection -> g_q (B,H,T,dh)
    gemm128_kernel<1><<<dim3(D_ / 128, M_ / 128), 256>>>(x, Wq, bq, nullptr);
    // K and V projections -> g_k, g_v
    kvproj_kernel<<<dim3(2, M_ / 128), 256>>>(xk, Wk, bk, xv, Wv, bv);
    // RoPE in-place on g_q and g_k
    {
        int total = B_ * H_ * T_ * 32 + B_ * T_ * 32;
        rope_kernel<<<(total + 255) / 256, 256>>>();
    }
    // tensor-core attention -> g_ctx (B,T,D)
    attn_tc_kernel<<<dim3(T_ / 64, H_, B_), 128, ATTN_SMEM>>>();
    // output projection -> d_out
    gemm128_kernel<0><<<dim3(D_ / 128, M_ / 128), 256>>>(nullptr, Wo, bo, out);
}